// round 5
// baseline (speedup 1.0000x reference)
#include <cuda_runtime.h>
#include <cuda_bf16.h>

// Shapes: x (64, 96, 8, 8) fp32 -> out (64, 96, 96, 8, 8, 2) fp32
// out[b,i,j,c1,c2,0] = x[b,i,c1,c2]; out[b,i,j,c1,c2,1] = x[b,j,c1,c2]
//
// One thread writes one float4 = {xi[k], xj[k], xi[k+1], xj[k+1]}.
// 32 float4 per (b,i,j) pair (64 k-values / 2 per float4).

#define B_DIM  64
#define GS_DIM 96
#define BLK    64          // 8*8 floats per group block
#define F4_PER_PAIR 32     // BLK/2 float4 per (b,i,j)

__global__ __launch_bounds__(256)
void gcom_kernel(const float* __restrict__ x, float4* __restrict__ out)
{
    // total float4 = 64*96*96*32 = 18,874,368 ; grid*block covers exactly.
    unsigned idx = blockIdx.x * 256u + threadIdx.x;

    unsigned k2 = idx & 31u;               // which float4 within the 64-elem block
    unsigned t  = idx >> 5;                // (b, i, j) flat
    unsigned j  = t % GS_DIM;
    unsigned u  = t / GS_DIM;              // (b, i) flat
    unsigned i  = u % GS_DIM;
    unsigned b  = u / GS_DIM;

    const float2* xi = (const float2*)(x + (b * GS_DIM + i) * BLK) + k2;
    const float2* xj = (const float2*)(x + (b * GS_DIM + j) * BLK) + k2;

    float2 a = __ldg(xi);
    float2 c = __ldg(xj);

    out[idx] = make_float4(a.x, c.x, a.y, c.y);
}

extern "C" void kernel_launch(void* const* d_in, const int* in_sizes, int n_in,
                              void* d_out, int out_size)
{
    const float* x = (const float*)d_in[0];
    float4* out = (float4*)d_out;

    // out_size = 75,497,472 floats -> 18,874,368 float4 -> 73,728 blocks of 256
    unsigned n4 = (unsigned)(out_size / 4);
    unsigned blocks = (n4 + 255u) / 256u;
    gcom_kernel<<<blocks, 256>>>(x, out);
}